// round 14
// baseline (speedup 1.0000x reference)
#include <cuda_runtime.h>
#include <cstdint>

// ---------------- scratch ----------------
__device__ float g_qkv [8LL * 768 * 1024];
__device__ float g_attn[8LL * 256 * 1024];

__device__ __forceinline__ unsigned cvt_tf32(float x) {
    unsigned r;
    asm("cvt.rna.tf32.f32 %0, %1;" : "=r"(r) : "f"(x));
    return r;
}
__device__ __forceinline__ void mma_tf32(float4& c, unsigned a0, unsigned a1,
                                         unsigned a2, unsigned a3,
                                         unsigned b0, unsigned b1) {
    asm volatile(
        "mma.sync.aligned.m16n8k8.row.col.f32.tf32.tf32.f32 "
        "{%0,%1,%2,%3}, {%4,%5,%6,%7}, {%8,%9}, {%0,%1,%2,%3};"
        : "+f"(c.x), "+f"(c.y), "+f"(c.z), "+f"(c.w)
        : "r"(a0), "r"(a1), "r"(a2), "r"(a3), "r"(b0), "r"(b1));
}

// ---------------- tf32 GEMM: 128x128 tile, BK=32, 8 warps, reg prefetch ----------------
__global__ __launch_bounds__(256) void sgemm_tf32(
    const float* __restrict__ A, const float* __restrict__ X,
    float* __restrict__ C, const float* __restrict__ bias,
    int M, int N, int K, long long sX, long long sC, int crow,
    float qscale, int qrows)
{
    __shared__ float As[32 * 136];
    __shared__ float Bs[32 * 136];
    const int bz = blockIdx.z;
    const float* Xb = X + (long long)bz * sX;
    float* Cb = C + (long long)bz * sC;
    const int row0 = blockIdx.y * 128, col0 = blockIdx.x * 128;
    const int t = threadIdx.x;
    const int wid = t >> 5, lane = t & 31;
    const int gid = lane >> 2, tig = lane & 3;
    const int wm = wid >> 1, wn = wid & 1;
    const int ar = t >> 1, aks = (t & 1) * 16;
    const int br = t >> 3, bc = (t & 7) * 4;
    const float* Ap = A + (long long)(row0 + ar) * K + aks;
    const float* Xp = Xb + (long long)br * N + col0 + bc;

    float4 pa[4], pb[4];
#pragma unroll
    for (int j = 0; j < 4; j++) {
        pa[j] = *(const float4*)(Ap + 4 * j);
        pb[j] = *(const float4*)(Xp + 32 * j);
    }
    float4 acc[2][8];
#pragma unroll
    for (int mt = 0; mt < 2; mt++)
#pragma unroll
        for (int nt = 0; nt < 8; nt++) acc[mt][nt] = make_float4(0.f, 0.f, 0.f, 0.f);

    for (int k0 = 0;; ) {
#pragma unroll
        for (int j = 0; j < 4; j++) {
            As[(aks + 4 * j + 0) * 136 + ar] = __uint_as_float(cvt_tf32(pa[j].x));
            As[(aks + 4 * j + 1) * 136 + ar] = __uint_as_float(cvt_tf32(pa[j].y));
            As[(aks + 4 * j + 2) * 136 + ar] = __uint_as_float(cvt_tf32(pa[j].z));
            As[(aks + 4 * j + 3) * 136 + ar] = __uint_as_float(cvt_tf32(pa[j].w));
            float4 bb;
            bb.x = __uint_as_float(cvt_tf32(pb[j].x));
            bb.y = __uint_as_float(cvt_tf32(pb[j].y));
            bb.z = __uint_as_float(cvt_tf32(pb[j].z));
            bb.w = __uint_as_float(cvt_tf32(pb[j].w));
            *(float4*)&Bs[br * 136 + bc + 32 * j] = bb;
        }
        __syncthreads();
        bool last = (k0 + 32 >= K);
        if (!last) {
#pragma unroll
            for (int j = 0; j < 4; j++) {
                pa[j] = *(const float4*)(Ap + k0 + 32 + 4 * j);
                pb[j] = *(const float4*)(Xp + (long long)(k0 + 32) * N + 32 * j);
            }
        }
#pragma unroll
        for (int ks = 0; ks < 4; ks++) {
            const int kk = ks * 8;
            unsigned a[2][4];
#pragma unroll
            for (int mt = 0; mt < 2; mt++) {
                int m0 = wm * 32 + mt * 16;
                a[mt][0] = __float_as_uint(As[(kk + tig) * 136 + m0 + gid]);
                a[mt][1] = __float_as_uint(As[(kk + tig) * 136 + m0 + gid + 8]);
                a[mt][2] = __float_as_uint(As[(kk + tig + 4) * 136 + m0 + gid]);
                a[mt][3] = __float_as_uint(As[(kk + tig + 4) * 136 + m0 + gid + 8]);
            }
#pragma unroll
            for (int nt = 0; nt < 8; nt++) {
                int n0 = wn * 64 + nt * 8;
                unsigned b0 = __float_as_uint(Bs[(kk + tig) * 136 + n0 + gid]);
                unsigned b1 = __float_as_uint(Bs[(kk + tig + 4) * 136 + n0 + gid]);
                mma_tf32(acc[0][nt], a[0][0], a[0][1], a[0][2], a[0][3], b0, b1);
                mma_tf32(acc[1][nt], a[1][0], a[1][1], a[1][2], a[1][3], b0, b1);
            }
        }
        __syncthreads();
        k0 += 32;
        if (last) break;
    }
#pragma unroll
    for (int mt = 0; mt < 2; mt++) {
        int rA = row0 + wm * 32 + mt * 16 + gid;
        int rB = rA + 8;
        float bA = bias ? bias[rA] : 0.f, bB = bias ? bias[rB] : 0.f;
        float sA = (rA < qrows) ? qscale : 1.f, sB = (rB < qrows) ? qscale : 1.f;
#pragma unroll
        for (int nt = 0; nt < 8; nt++) {
            int cc = col0 + wn * 64 + nt * 8 + 2 * tig;
            *(float2*)&Cb[(long long)(crow + rA) * N + cc] =
                make_float2((acc[mt][nt].x + bA) * sA, (acc[mt][nt].y + bA) * sA);
            *(float2*)&Cb[(long long)(crow + rB) * N + cc] =
                make_float2((acc[mt][nt].z + bB) * sB, (acc[mt][nt].w + bB) * sB);
        }
    }
}

// ---------------- implicit-im2col conv GEMM (3x3 pad1 on 32x32), 128x128 tile ----------------
__global__ __launch_bounds__(256) void conv_gemm_tf32(
    const float* __restrict__ A, const float* __restrict__ x,
    float* __restrict__ C, const float* __restrict__ bias,
    long long sC)
{
    const int N = 1024, K = 2304;
    __shared__ float As[32 * 136];
    __shared__ float Bs[32 * 136];
    const int bz = blockIdx.z;
    const float* Xb = x + (long long)bz * 256 * 1024;
    float* Cb = C + (long long)bz * sC;
    const int row0 = blockIdx.y * 128, col0 = blockIdx.x * 128;
    const int t = threadIdx.x;
    const int wid = t >> 5, lane = t & 31;
    const int gid = lane >> 2, tig = lane & 3;
    const int wm = wid >> 1, wn = wid & 1;
    const int ar = t >> 1, aks = (t & 1) * 16;
    const int br = t >> 3, bc = (t & 7) * 4;
    const float* Ap = A + (long long)(row0 + ar) * K + aks;

    float4 pa[4];
    float pbv[16];
#pragma unroll
    for (int j = 0; j < 4; j++) pa[j] = *(const float4*)(Ap + 4 * j);

    auto loadB = [&](int k0) {
        int k = k0 + br;
        int ci = k / 9, r = k - 9 * ci;
        int kh = r / 3, kw = r - 3 * kh;
        const float* xp = Xb + (long long)ci * 1024 + (kh - 1) * 32 + (kw - 1);
#pragma unroll
        for (int j = 0; j < 4; j++) {
#pragma unroll
            for (int i = 0; i < 4; i++) {
                int n = col0 + bc + 32 * j + i;
                int y = n >> 5, xx = n & 31;
                bool ok = (y + kh >= 1) && (y + kh <= 32) && (xx + kw >= 1) && (xx + kw <= 32);
                pbv[j * 4 + i] = ok ? xp[n] : 0.f;
            }
        }
    };
    loadB(0);

    float4 acc[2][8];
#pragma unroll
    for (int mt = 0; mt < 2; mt++)
#pragma unroll
        for (int nt = 0; nt < 8; nt++) acc[mt][nt] = make_float4(0.f, 0.f, 0.f, 0.f);

    for (int k0 = 0;; ) {
#pragma unroll
        for (int j = 0; j < 4; j++) {
            As[(aks + 4 * j + 0) * 136 + ar] = __uint_as_float(cvt_tf32(pa[j].x));
            As[(aks + 4 * j + 1) * 136 + ar] = __uint_as_float(cvt_tf32(pa[j].y));
            As[(aks + 4 * j + 2) * 136 + ar] = __uint_as_float(cvt_tf32(pa[j].z));
            As[(aks + 4 * j + 3) * 136 + ar] = __uint_as_float(cvt_tf32(pa[j].w));
            float4 bb;
            bb.x = __uint_as_float(cvt_tf32(pbv[j * 4 + 0]));
            bb.y = __uint_as_float(cvt_tf32(pbv[j * 4 + 1]));
            bb.z = __uint_as_float(cvt_tf32(pbv[j * 4 + 2]));
            bb.w = __uint_as_float(cvt_tf32(pbv[j * 4 + 3]));
            *(float4*)&Bs[br * 136 + bc + 32 * j] = bb;
        }
        __syncthreads();
        bool last = (k0 + 32 >= K);
        if (!last) {
#pragma unroll
            for (int j = 0; j < 4; j++) pa[j] = *(const float4*)(Ap + k0 + 32 + 4 * j);
            loadB(k0 + 32);
        }
#pragma unroll
        for (int ks = 0; ks < 4; ks++) {
            const int kk = ks * 8;
            unsigned a[2][4];
#pragma unroll
            for (int mt = 0; mt < 2; mt++) {
                int m0 = wm * 32 + mt * 16;
                a[mt][0] = __float_as_uint(As[(kk + tig) * 136 + m0 + gid]);
                a[mt][1] = __float_as_uint(As[(kk + tig) * 136 + m0 + gid + 8]);
                a[mt][2] = __float_as_uint(As[(kk + tig + 4) * 136 + m0 + gid]);
                a[mt][3] = __float_as_uint(As[(kk + tig + 4) * 136 + m0 + gid + 8]);
            }
#pragma unroll
            for (int nt = 0; nt < 8; nt++) {
                int n0 = wn * 64 + nt * 8;
                unsigned b0 = __float_as_uint(Bs[(kk + tig) * 136 + n0 + gid]);
                unsigned b1 = __float_as_uint(Bs[(kk + tig + 4) * 136 + n0 + gid]);
                mma_tf32(acc[0][nt], a[0][0], a[0][1], a[0][2], a[0][3], b0, b1);
                mma_tf32(acc[1][nt], a[1][0], a[1][1], a[1][2], a[1][3], b0, b1);
            }
        }
        __syncthreads();
        k0 += 32;
        if (last) break;
    }
#pragma unroll
    for (int mt = 0; mt < 2; mt++) {
        int rA = row0 + wm * 32 + mt * 16 + gid;
        int rB = rA + 8;
        float bA = bias[rA], bB = bias[rB];
#pragma unroll
        for (int nt = 0; nt < 8; nt++) {
            int cc = col0 + wn * 64 + nt * 8 + 2 * tig;
            *(float2*)&Cb[(long long)rA * N + cc] =
                make_float2(acc[mt][nt].x + bA, acc[mt][nt].y + bA);
            *(float2*)&Cb[(long long)rB * N + cc] =
                make_float2(acc[mt][nt].z + bB, acc[mt][nt].w + bB);
        }
    }
}

// ---------------- tensor-core flash attention, fixed-max softmax, vectorized K frags ----------------
// K region: K[d][key] at d*96 + (key&7)*12 + (key>>3)   (32*96 = 3072 floats)
// V region: V[dv][key] at VO + dv*72 + key               (2304 floats)
#define VO   3072
#define APO  5376
#define AEH  9984
#define ASC  12032
#define A_SM_FLOATS 12096

__global__ __launch_bounds__(128) void attn_mma(
    const float* __restrict__ qkv,
    const float* __restrict__ relw,   // [63][32]
    const float* __restrict__ relh,   // [63][32]
    float* __restrict__ attn_out)     // [B][256][1024]
{
    extern __shared__ float sm[];
    const int bh = blockIdx.y;
    const int b = bh >> 3, h = bh & 7;
    const int bx = blockIdx.x;
    const int q0 = bx * 64;
    const int t = threadIdx.x;
    const int wid = t >> 5, lane = t & 31;
    const int gid = lane >> 2, tig = lane & 3;
    const int qrow = wid * 16;

    const float* qb = qkv + ((long long)b * 768 +       h * 32) * 1024;
    const float* kb = qkv + ((long long)b * 768 + 256 + h * 32) * 1024;
    const float* vb = qkv + ((long long)b * 768 + 512 + h * 32) * 1024;

    // prologue: Q [q][36] staged in K region; rel tables stride 36 in P region
    for (int i = t; i < 2048; i += 128) {
        int d = i >> 6, qi = i & 63;
        sm[qi * 36 + d] = qb[d * 1024 + q0 + qi];
    }
    for (int i = t; i < 2016; i += 128) {
        int m = i >> 5, d = i & 31;
        sm[APO + m * 36 + d]        = relw[i];
        sm[APO + 2268 + m * 36 + d] = relh[i];
    }
    __syncthreads();

    // eh2[qi][xk] = eh[qi][xk - hq(qi) + 31]
    for (int e = t; e < 2048; e += 128) {
        int qi = e >> 5, xk = e & 31;
        int m = xk - (2 * bx + (qi >> 5)) + 31;
        const float* qp = sm + qi * 36;
        const float* rp = sm + APO + 2268 + m * 36;
        float s = 0.f;
#pragma unroll
        for (int d = 0; d < 32; d += 4) {
            float4 q4 = *(const float4*)(qp + d);
            float4 r4 = *(const float4*)(rp + d);
            s += q4.x * r4.x + q4.y * r4.y + q4.z * r4.z + q4.w * r4.w;
        }
        sm[AEH + e] = s;
    }

    const int qiA = qrow + gid, qiB = qiA + 8;
    unsigned qa[4][4];
#pragma unroll
    for (int ks = 0; ks < 4; ks++) {
        int kd = ks * 8;
        qa[ks][0] = cvt_tf32(sm[qiA * 36 + kd + tig]);
        qa[ks][1] = cvt_tf32(sm[qiB * 36 + kd + tig]);
        qa[ks][2] = cvt_tf32(sm[qiA * 36 + kd + tig + 4]);
        qa[ks][3] = cvt_tf32(sm[qiB * 36 + kd + tig + 4]);
    }
    float ewreg[2][8];
#pragma unroll
    for (int rr = 0; rr < 2; rr++) {
        int qi = rr ? qiB : qiA;
        const float* qp = sm + qi * 36;
#pragma unroll
        for (int e = 0; e < 8; e++) {
            int yk = (e >> 1) * 8 + tig * 2 + (e & 1);
            int m = yk - (qi & 31) + 31;
            const float* rp = sm + APO + m * 36;
            float s = 0.f;
#pragma unroll
            for (int d = 0; d < 32; d += 4) {
                float4 q4 = *(const float4*)(qp + d);
                float4 r4 = *(const float4*)(rp + d);
                s += q4.x * r4.x + q4.y * r4.y + q4.z * r4.z + q4.w * r4.w;
            }
            ewreg[rr][e] = s;
        }
    }
    __syncthreads();

    // stage tile 0: K scattered into fragment-friendly layout, V contiguous
    {
        float4 kr0[4], vr0[4];
#pragma unroll
        for (int j = 0; j < 4; j++) {
            int fi = j * 128 + t, d = fi >> 4, c = (fi & 15) * 4;
            kr0[j] = *(const float4*)(kb + d * 1024 + c);
            vr0[j] = *(const float4*)(vb + d * 1024 + c);
        }
#pragma unroll
        for (int j = 0; j < 4; j++) {
            int fi = j * 128 + t, d = fi >> 4, c = (fi & 15) * 4;
            int kbase = d * 96 + (c & 7) * 12 + (c >> 3);
            sm[kbase]      = kr0[j].x;
            sm[kbase + 12] = kr0[j].y;
            sm[kbase + 24] = kr0[j].z;
            sm[kbase + 36] = kr0[j].w;
            *(float4*)&sm[VO + d * 72 + c] = vr0[j];
        }
    }
    __syncthreads();

    float sA = 0.f, sB = 0.f;     // fixed-max softmax
    float4 oc[2][2];
#pragma unroll
    for (int mt = 0; mt < 2; mt++)
#pragma unroll
        for (int n2 = 0; n2 < 2; n2++) oc[mt][n2] = make_float4(0.f, 0.f, 0.f, 0.f);

    float4 kr[4], vr[4];
    for (int tile = 0; tile < 16; tile++) {
        const bool more = (tile < 15);
        if (more) {
            int k0n = (tile + 1) * 64;
#pragma unroll
            for (int j = 0; j < 4; j++) {
                int fi = j * 128 + t, d = fi >> 4, c = (fi & 15) * 4;
                kr[j] = *(const float4*)(kb + d * 1024 + k0n + c);
                vr[j] = *(const float4*)(vb + d * 1024 + k0n + c);
            }
        }

        // S = Q K^T with vectorized B-fragment loads
        float4 sc4[8];
#pragma unroll
        for (int nt = 0; nt < 8; nt++) sc4[nt] = make_float4(0.f, 0.f, 0.f, 0.f);
#pragma unroll
        for (int ks = 0; ks < 4; ks++) {
            int kd = ks * 8;
            const float* k0p = sm + (kd + tig) * 96 + gid * 12;
            const float* k1p = sm + (kd + tig + 4) * 96 + gid * 12;
            float4 b0lo = *(const float4*)(k0p);
            float4 b0hi = *(const float4*)(k0p + 4);
            float4 b1lo = *(const float4*)(k1p);
            float4 b1hi = *(const float4*)(k1p + 4);
            float b0v[8] = {b0lo.x, b0lo.y, b0lo.z, b0lo.w, b0hi.x, b0hi.y, b0hi.z, b0hi.w};
            float b1v[8] = {b1lo.x, b1lo.y, b1lo.z, b1lo.w, b1hi.x, b1hi.y, b1hi.z, b1hi.w};
#pragma unroll
            for (int nt = 0; nt < 8; nt++) {
                mma_tf32(sc4[nt], qa[ks][0], qa[ks][1], qa[ks][2], qa[ks][3],
                         __float_as_uint(b0v[nt]), __float_as_uint(b1v[nt]));
            }
        }

        // rel add + exp, accumulate row sums, store P
        int xk = tile * 2;
        float ehA0 = sm[AEH + qiA * 32 + xk];
        float ehA1 = sm[AEH + qiA * 32 + xk + 1];
        float ehB0 = sm[AEH + qiB * 32 + xk];
        float ehB1 = sm[AEH + qiB * 32 + xk + 1];
        float rsA = 0.f, rsB = 0.f;
#pragma unroll
        for (int nt = 0; nt < 8; nt++) {
            float ha = (nt < 4) ? ehA0 : ehA1;
            float hb = (nt < 4) ? ehB0 : ehB1;
            float px = __expf(sc4[nt].x + ewreg[0][(nt & 3) * 2 + 0] + ha);
            float py = __expf(sc4[nt].y + ewreg[0][(nt & 3) * 2 + 1] + ha);
            float pz = __expf(sc4[nt].z + ewreg[1][(nt & 3) * 2 + 0] + hb);
            float pw = __expf(sc4[nt].w + ewreg[1][(nt & 3) * 2 + 1] + hb);
            rsA += px + py; rsB += pz + pw;
            int cc = nt * 8 + 2 * tig;
            *(float2*)&sm[APO + qiA * 72 + cc] = make_float2(px, py);
            *(float2*)&sm[APO + qiB * 72 + cc] = make_float2(pz, pw);
        }
        sA += rsA; sB += rsB;
        __syncwarp();

        // O^T += V P^T
#pragma unroll
        for (int ks = 0; ks < 8; ks++) {
            int kk = ks * 8;
            unsigned p0[2], p1[2];
#pragma unroll
            for (int n2 = 0; n2 < 2; n2++) {
                p0[n2] = __float_as_uint(sm[APO + (qrow + n2 * 8 + gid) * 72 + kk + tig]);
                p1[n2] = __float_as_uint(sm[APO + (qrow + n2 * 8 + gid) * 72 + kk + tig + 4]);
            }
#pragma unroll
            for (int mt = 0; mt < 2; mt++) {
                int dv0 = mt * 16;
                unsigned a0 = __float_as_uint(sm[VO + (dv0 + gid) * 72 + kk + tig]);
                unsigned a1 = __float_as_uint(sm[VO + (dv0 + gid + 8) * 72 + kk + tig]);
                unsigned a2 = __float_as_uint(sm[VO + (dv0 + gid) * 72 + kk + tig + 4]);
                unsigned a3 = __float_as_uint(sm[VO + (dv0 + gid + 8) * 72 + kk + tig + 4]);
                mma_tf32(oc[mt][0], a0, a1, a2, a3, p0[0], p1[0]);
                mma_tf32(oc[mt][1], a0, a1, a2, a3, p0[1], p1[1]);
            }
        }

        __syncthreads();
        if (more) {
#pragma unroll
            for (int j = 0; j < 4; j++) {
                int fi = j * 128 + t, d = fi >> 4, c = (fi & 15) * 4;
                int kbase = d * 96 + (c & 7) * 12 + (c >> 3);
                sm[kbase]      = kr[j].x;
                sm[kbase + 12] = kr[j].y;
                sm[kbase + 24] = kr[j].z;
                sm[kbase + 36] = kr[j].w;
                *(float4*)&sm[VO + d * 72 + c] = vr[j];
            }
        }
        __syncthreads();
    }

    // reduce row sums across tig lanes, broadcast 1/sum
    sA += __shfl_xor_sync(0xffffffffu, sA, 1);
    sA += __shfl_xor_sync(0xffffffffu, sA, 2);
    sB += __shfl_xor_sync(0xffffffffu, sB, 1);
    sB += __shfl_xor_sync(0xffffffffu, sB, 2);
    if (tig == 0) { sm[ASC + qiA] = 1.f / sA; sm[ASC + qiB] = 1.f / sB; }
    __syncwarp();
    float si[2][2];
#pragma unroll
    for (int n2 = 0; n2 < 2; n2++)
#pragma unroll
        for (int j = 0; j < 2; j++)
            si[n2][j] = sm[ASC + qrow + n2 * 8 + 2 * tig + j];
    float* ob = attn_out + ((long long)b * 256 + h * 32) * 1024 + q0;
#pragma unroll
    for (int mt = 0; mt < 2; mt++)
#pragma unroll
        for (int n2 = 0; n2 < 2; n2++) {
            int dv0 = mt * 16 + gid;
            int qq = qrow + n2 * 8 + 2 * tig;
            *(float2*)&ob[(long long)dv0 * 1024 + qq] =
                make_float2(oc[mt][n2].x * si[n2][0], oc[mt][n2].y * si[n2][1]);
            *(float2*)&ob[(long long)(dv0 + 8) * 1024 + qq] =
                make_float2(oc[mt][n2].z * si[n2][0], oc[mt][n2].w * si[n2][1]);
        }
}

// ---------------- launch: R9 schedule (conv on one side stream) ----------------
extern "C" void kernel_launch(void* const* d_in, const int* in_sizes, int n_in,
                              void* d_out, int out_size) {
    const float* x      = (const float*)d_in[0];
    const float* w_qkv  = (const float*)d_in[1];
    const float* b_qkv  = (const float*)d_in[2];
    const float* w_attn = (const float*)d_in[3];
    const float* b_attn = (const float*)d_in[4];
    const float* w_out  = (const float*)d_in[5];
    const float* b_out  = (const float*)d_in[6];
    const float* relw   = (const float*)d_in[7];
    const float* relh   = (const float*)d_in[8];
    float* out = (float*)d_out;

    float *qkv, *attn;
    cudaGetSymbolAddress((void**)&qkv,  g_qkv);
    cudaGetSymbolAddress((void**)&attn, g_attn);

    const int A_SMEM = A_SM_FLOATS * 4;   // 48384
    cudaFuncSetAttribute(attn_mma, cudaFuncAttributeMaxDynamicSharedMemorySize, A_SMEM);

    cudaStream_t s1;
    cudaEvent_t e0, e1;
    cudaStreamCreateWithFlags(&s1, cudaStreamNonBlocking);
    cudaEventCreateWithFlags(&e0, cudaEventDisableTiming);
    cudaEventCreateWithFlags(&e1, cudaEventDisableTiming);

    // fork: conv path on side stream
    cudaEventRecord(e0, 0);
    cudaStreamWaitEvent(s1, e0, 0);
    conv_gemm_tf32<<<dim3(8, 2, 8), 256, 0, s1>>>(w_out, x, out, b_out, 512LL * 1024);
    cudaEventRecord(e1, s1);

    // main chain on the capture stream
    sgemm_tf32<<<dim3(8, 6, 8), 256>>>(w_qkv, x, qkv, b_qkv,
                                       768, 1024, 256,
                                       256LL * 1024, 768LL * 1024, 0,
                                       0.17677669529663687f, 256);
    attn_mma<<<dim3(16, 64), 128, A_SMEM>>>(qkv, relw, relh, attn);
    sgemm_tf32<<<dim3(8, 2, 8), 256>>>(w_attn, attn, out, b_attn,
                                       256, 1024, 256,
                                       256LL * 1024, 512LL * 1024, 256,
                                       1.f, 0);

    // join
    cudaStreamWaitEvent(0, e1, 0);

    cudaStreamCaptureStatus st = cudaStreamCaptureStatusNone;
    cudaStreamIsCapturing(s1, &st);
    if (st == cudaStreamCaptureStatusNone) {
        cudaStreamDestroy(s1);
        cudaEventDestroy(e0);
        cudaEventDestroy(e1);
    }
}

// round 15
// speedup vs baseline: 1.0343x; 1.0343x over previous
#include <cuda_runtime.h>
#include <cstdint>

// ---------------- scratch ----------------
__device__ float g_qkv [8LL * 768 * 1024];
__device__ float g_attn[8LL * 256 * 1024];

__device__ __forceinline__ unsigned cvt_tf32(float x) {
    unsigned r;
    asm("cvt.rna.tf32.f32 %0, %1;" : "=r"(r) : "f"(x));
    return r;
}
__device__ __forceinline__ void mma_tf32(float4& c, unsigned a0, unsigned a1,
                                         unsigned a2, unsigned a3,
                                         unsigned b0, unsigned b1) {
    asm volatile(
        "mma.sync.aligned.m16n8k8.row.col.f32.tf32.tf32.f32 "
        "{%0,%1,%2,%3}, {%4,%5,%6,%7}, {%8,%9}, {%0,%1,%2,%3};"
        : "+f"(c.x), "+f"(c.y), "+f"(c.z), "+f"(c.w)
        : "r"(a0), "r"(a1), "r"(a2), "r"(a3), "r"(b0), "r"(b1));
}

// ---------------- tf32 GEMM: 128x128 tile, BK=32, 8 warps, reg prefetch ----------------
__global__ __launch_bounds__(256) void sgemm_tf32(
    const float* __restrict__ A, const float* __restrict__ X,
    float* __restrict__ C, const float* __restrict__ bias,
    int M, int N, int K, long long sX, long long sC, int crow,
    float qscale, int qrows)
{
    __shared__ float As[32 * 136];
    __shared__ float Bs[32 * 136];
    const int bz = blockIdx.z;
    const float* Xb = X + (long long)bz * sX;
    float* Cb = C + (long long)bz * sC;
    const int row0 = blockIdx.y * 128, col0 = blockIdx.x * 128;
    const int t = threadIdx.x;
    const int wid = t >> 5, lane = t & 31;
    const int gid = lane >> 2, tig = lane & 3;
    const int wm = wid >> 1, wn = wid & 1;
    const int ar = t >> 1, aks = (t & 1) * 16;
    const int br = t >> 3, bc = (t & 7) * 4;
    const float* Ap = A + (long long)(row0 + ar) * K + aks;
    const float* Xp = Xb + (long long)br * N + col0 + bc;

    float4 pa[4], pb[4];
#pragma unroll
    for (int j = 0; j < 4; j++) {
        pa[j] = *(const float4*)(Ap + 4 * j);
        pb[j] = *(const float4*)(Xp + 32 * j);
    }
    float4 acc[2][8];
#pragma unroll
    for (int mt = 0; mt < 2; mt++)
#pragma unroll
        for (int nt = 0; nt < 8; nt++) acc[mt][nt] = make_float4(0.f, 0.f, 0.f, 0.f);

    for (int k0 = 0;; ) {
#pragma unroll
        for (int j = 0; j < 4; j++) {
            As[(aks + 4 * j + 0) * 136 + ar] = __uint_as_float(cvt_tf32(pa[j].x));
            As[(aks + 4 * j + 1) * 136 + ar] = __uint_as_float(cvt_tf32(pa[j].y));
            As[(aks + 4 * j + 2) * 136 + ar] = __uint_as_float(cvt_tf32(pa[j].z));
            As[(aks + 4 * j + 3) * 136 + ar] = __uint_as_float(cvt_tf32(pa[j].w));
            float4 bb;
            bb.x = __uint_as_float(cvt_tf32(pb[j].x));
            bb.y = __uint_as_float(cvt_tf32(pb[j].y));
            bb.z = __uint_as_float(cvt_tf32(pb[j].z));
            bb.w = __uint_as_float(cvt_tf32(pb[j].w));
            *(float4*)&Bs[br * 136 + bc + 32 * j] = bb;
        }
        __syncthreads();
        bool last = (k0 + 32 >= K);
        if (!last) {
#pragma unroll
            for (int j = 0; j < 4; j++) {
                pa[j] = *(const float4*)(Ap + k0 + 32 + 4 * j);
                pb[j] = *(const float4*)(Xp + (long long)(k0 + 32) * N + 32 * j);
            }
        }
#pragma unroll
        for (int ks = 0; ks < 4; ks++) {
            const int kk = ks * 8;
            unsigned a[2][4];
#pragma unroll
            for (int mt = 0; mt < 2; mt++) {
                int m0 = wm * 32 + mt * 16;
                a[mt][0] = __float_as_uint(As[(kk + tig) * 136 + m0 + gid]);
                a[mt][1] = __float_as_uint(As[(kk + tig) * 136 + m0 + gid + 8]);
                a[mt][2] = __float_as_uint(As[(kk + tig + 4) * 136 + m0 + gid]);
                a[mt][3] = __float_as_uint(As[(kk + tig + 4) * 136 + m0 + gid + 8]);
            }
#pragma unroll
            for (int nt = 0; nt < 8; nt++) {
                int n0 = wn * 64 + nt * 8;
                unsigned b0 = __float_as_uint(Bs[(kk + tig) * 136 + n0 + gid]);
                unsigned b1 = __float_as_uint(Bs[(kk + tig + 4) * 136 + n0 + gid]);
                mma_tf32(acc[0][nt], a[0][0], a[0][1], a[0][2], a[0][3], b0, b1);
                mma_tf32(acc[1][nt], a[1][0], a[1][1], a[1][2], a[1][3], b0, b1);
            }
        }
        __syncthreads();
        k0 += 32;
        if (last) break;
    }
#pragma unroll
    for (int mt = 0; mt < 2; mt++) {
        int rA = row0 + wm * 32 + mt * 16 + gid;
        int rB = rA + 8;
        float bA = bias ? bias[rA] : 0.f, bB = bias ? bias[rB] : 0.f;
        float sA = (rA < qrows) ? qscale : 1.f, sB = (rB < qrows) ? qscale : 1.f;
#pragma unroll
        for (int nt = 0; nt < 8; nt++) {
            int cc = col0 + wn * 64 + nt * 8 + 2 * tig;
            *(float2*)&Cb[(long long)(crow + rA) * N + cc] =
                make_float2((acc[mt][nt].x + bA) * sA, (acc[mt][nt].y + bA) * sA);
            *(float2*)&Cb[(long long)(crow + rB) * N + cc] =
                make_float2((acc[mt][nt].z + bB) * sB, (acc[mt][nt].w + bB) * sB);
        }
    }
}

// ---------------- implicit-im2col conv GEMM (3x3 pad1 on 32x32), 128x128 tile ----------------
__global__ __launch_bounds__(256) void conv_gemm_tf32(
    const float* __restrict__ A, const float* __restrict__ x,
    float* __restrict__ C, const float* __restrict__ bias,
    long long sC)
{
    const int N = 1024, K = 2304;
    __shared__ float As[32 * 136];
    __shared__ float Bs[32 * 136];
    const int bz = blockIdx.z;
    const float* Xb = x + (long long)bz * 256 * 1024;
    float* Cb = C + (long long)bz * sC;
    const int row0 = blockIdx.y * 128, col0 = blockIdx.x * 128;
    const int t = threadIdx.x;
    const int wid = t >> 5, lane = t & 31;
    const int gid = lane >> 2, tig = lane & 3;
    const int wm = wid >> 1, wn = wid & 1;
    const int ar = t >> 1, aks = (t & 1) * 16;
    const int br = t >> 3, bc = (t & 7) * 4;
    const float* Ap = A + (long long)(row0 + ar) * K + aks;

    float4 pa[4];
    float pbv[16];
#pragma unroll
    for (int j = 0; j < 4; j++) pa[j] = *(const float4*)(Ap + 4 * j);

    auto loadB = [&](int k0) {
        int k = k0 + br;
        int ci = k / 9, r = k - 9 * ci;
        int kh = r / 3, kw = r - 3 * kh;
        const float* xp = Xb + (long long)ci * 1024 + (kh - 1) * 32 + (kw - 1);
#pragma unroll
        for (int j = 0; j < 4; j++) {
#pragma unroll
            for (int i = 0; i < 4; i++) {
                int n = col0 + bc + 32 * j + i;
                int y = n >> 5, xx = n & 31;
                bool ok = (y + kh >= 1) && (y + kh <= 32) && (xx + kw >= 1) && (xx + kw <= 32);
                pbv[j * 4 + i] = ok ? xp[n] : 0.f;
            }
        }
    };
    loadB(0);

    float4 acc[2][8];
#pragma unroll
    for (int mt = 0; mt < 2; mt++)
#pragma unroll
        for (int nt = 0; nt < 8; nt++) acc[mt][nt] = make_float4(0.f, 0.f, 0.f, 0.f);

    for (int k0 = 0;; ) {
#pragma unroll
        for (int j = 0; j < 4; j++) {
            As[(aks + 4 * j + 0) * 136 + ar] = __uint_as_float(cvt_tf32(pa[j].x));
            As[(aks + 4 * j + 1) * 136 + ar] = __uint_as_float(cvt_tf32(pa[j].y));
            As[(aks + 4 * j + 2) * 136 + ar] = __uint_as_float(cvt_tf32(pa[j].z));
            As[(aks + 4 * j + 3) * 136 + ar] = __uint_as_float(cvt_tf32(pa[j].w));
            float4 bb;
            bb.x = __uint_as_float(cvt_tf32(pbv[j * 4 + 0]));
            bb.y = __uint_as_float(cvt_tf32(pbv[j * 4 + 1]));
            bb.z = __uint_as_float(cvt_tf32(pbv[j * 4 + 2]));
            bb.w = __uint_as_float(cvt_tf32(pbv[j * 4 + 3]));
            *(float4*)&Bs[br * 136 + bc + 32 * j] = bb;
        }
        __syncthreads();
        bool last = (k0 + 32 >= K);
        if (!last) {
#pragma unroll
            for (int j = 0; j < 4; j++) pa[j] = *(const float4*)(Ap + k0 + 32 + 4 * j);
            loadB(k0 + 32);
        }
#pragma unroll
        for (int ks = 0; ks < 4; ks++) {
            const int kk = ks * 8;
            unsigned a[2][4];
#pragma unroll
            for (int mt = 0; mt < 2; mt++) {
                int m0 = wm * 32 + mt * 16;
                a[mt][0] = __float_as_uint(As[(kk + tig) * 136 + m0 + gid]);
                a[mt][1] = __float_as_uint(As[(kk + tig) * 136 + m0 + gid + 8]);
                a[mt][2] = __float_as_uint(As[(kk + tig + 4) * 136 + m0 + gid]);
                a[mt][3] = __float_as_uint(As[(kk + tig + 4) * 136 + m0 + gid + 8]);
            }
#pragma unroll
            for (int nt = 0; nt < 8; nt++) {
                int n0 = wn * 64 + nt * 8;
                unsigned b0 = __float_as_uint(Bs[(kk + tig) * 136 + n0 + gid]);
                unsigned b1 = __float_as_uint(Bs[(kk + tig + 4) * 136 + n0 + gid]);
                mma_tf32(acc[0][nt], a[0][0], a[0][1], a[0][2], a[0][3], b0, b1);
                mma_tf32(acc[1][nt], a[1][0], a[1][1], a[1][2], a[1][3], b0, b1);
            }
        }
        __syncthreads();
        k0 += 32;
        if (last) break;
    }
#pragma unroll
    for (int mt = 0; mt < 2; mt++) {
        int rA = row0 + wm * 32 + mt * 16 + gid;
        int rB = rA + 8;
        float bA = bias[rA], bB = bias[rB];
#pragma unroll
        for (int nt = 0; nt < 8; nt++) {
            int cc = col0 + wn * 64 + nt * 8 + 2 * tig;
            *(float2*)&Cb[(long long)rA * N + cc] =
                make_float2(acc[mt][nt].x + bA, acc[mt][nt].y + bA);
            *(float2*)&Cb[(long long)rB * N + cc] =
                make_float2(acc[mt][nt].z + bB, acc[mt][nt].w + bB);
        }
    }
}

// ---------------- tensor-core flash attention, fixed-max softmax, 5 blocks/SM ----------------
#define APO  4608
#define AEH  9216
#define ASC  11264
#define A_SM_FLOATS 11328

__global__ __launch_bounds__(128, 5) void attn_mma(
    const float* __restrict__ qkv,
    const float* __restrict__ relw,   // [63][32]
    const float* __restrict__ relh,   // [63][32]
    float* __restrict__ attn_out)     // [B][256][1024]
{
    extern __shared__ float sm[];
    const int bh = blockIdx.y;
    const int b = bh >> 3, h = bh & 7;
    const int bx = blockIdx.x;
    const int q0 = bx * 64;
    const int t = threadIdx.x;
    const int wid = t >> 5, lane = t & 31;
    const int gid = lane >> 2, tig = lane & 3;
    const int qrow = wid * 16;

    const float* qb = qkv + ((long long)b * 768 +       h * 32) * 1024;
    const float* kb = qkv + ((long long)b * 768 + 256 + h * 32) * 1024;
    const float* vb = qkv + ((long long)b * 768 + 512 + h * 32) * 1024;

    for (int i = t; i < 2048; i += 128) {
        int d = i >> 6, qi = i & 63;
        sm[qi * 36 + d] = qb[d * 1024 + q0 + qi];
    }
    for (int i = t; i < 2016; i += 128) {
        int m = i >> 5, d = i & 31;
        sm[APO + m * 36 + d]        = relw[i];
        sm[APO + 2268 + m * 36 + d] = relh[i];
    }
    __syncthreads();

    // eh2[qi][xk] = eh[qi][xk - hq(qi) + 31]
    for (int e = t; e < 2048; e += 128) {
        int qi = e >> 5, xk = e & 31;
        int m = xk - (2 * bx + (qi >> 5)) + 31;
        const float* qp = sm + qi * 36;
        const float* rp = sm + APO + 2268 + m * 36;
        float s = 0.f;
#pragma unroll
        for (int d = 0; d < 32; d += 4) {
            float4 q4 = *(const float4*)(qp + d);
            float4 r4 = *(const float4*)(rp + d);
            s += q4.x * r4.x + q4.y * r4.y + q4.z * r4.z + q4.w * r4.w;
        }
        sm[AEH + e] = s;
    }

    const int qiA = qrow + gid, qiB = qiA + 8;
    unsigned qa[4][4];
#pragma unroll
    for (int ks = 0; ks < 4; ks++) {
        int kd = ks * 8;
        qa[ks][0] = cvt_tf32(sm[qiA * 36 + kd + tig]);
        qa[ks][1] = cvt_tf32(sm[qiB * 36 + kd + tig]);
        qa[ks][2] = cvt_tf32(sm[qiA * 36 + kd + tig + 4]);
        qa[ks][3] = cvt_tf32(sm[qiB * 36 + kd + tig + 4]);
    }
    float ewreg[2][8];
#pragma unroll
    for (int rr = 0; rr < 2; rr++) {
        int qi = rr ? qiB : qiA;
        const float* qp = sm + qi * 36;
#pragma unroll
        for (int e = 0; e < 8; e++) {
            int yk = (e >> 1) * 8 + tig * 2 + (e & 1);
            int m = yk - (qi & 31) + 31;
            const float* rp = sm + APO + m * 36;
            float s = 0.f;
#pragma unroll
            for (int d = 0; d < 32; d += 4) {
                float4 q4 = *(const float4*)(qp + d);
                float4 r4 = *(const float4*)(rp + d);
                s += q4.x * r4.x + q4.y * r4.y + q4.z * r4.z + q4.w * r4.w;
            }
            ewreg[rr][e] = s;
        }
    }
    __syncthreads();

    // stage tile 0
    {
        float4 kr0[4], vr0[4];
#pragma unroll
        for (int j = 0; j < 4; j++) {
            int fi = j * 128 + t, d = fi >> 4, c = (fi & 15) * 4;
            kr0[j] = *(const float4*)(kb + d * 1024 + c);
            vr0[j] = *(const float4*)(vb + d * 1024 + c);
        }
#pragma unroll
        for (int j = 0; j < 4; j++) {
            int fi = j * 128 + t, d = fi >> 4, c = (fi & 15) * 4;
            *(float4*)&sm[d * 72 + c]        = kr0[j];
            *(float4*)&sm[2304 + d * 72 + c] = vr0[j];
        }
    }
    __syncthreads();

    float sA = 0.f, sB = 0.f;     // fixed-max softmax (logits bounded; no overflow in fp32)
    float4 oc[2][2];
#pragma unroll
    for (int mt = 0; mt < 2; mt++)
#pragma unroll
        for (int n2 = 0; n2 < 2; n2++) oc[mt][n2] = make_float4(0.f, 0.f, 0.f, 0.f);

    float4 kr[4], vr[4];
    for (int tile = 0; tile < 16; tile++) {
        const bool more = (tile < 15);
        if (more) {
            int k0n = (tile + 1) * 64;
#pragma unroll
            for (int j = 0; j < 4; j++) {
                int fi = j * 128 + t, d = fi >> 4, c = (fi & 15) * 4;
                kr[j] = *(const float4*)(kb + d * 1024 + k0n + c);
                vr[j] = *(const float4*)(vb + d * 1024 + k0n + c);
            }
        }

        float4 sc4[8];
#pragma unroll
        for (int nt = 0; nt < 8; nt++) sc4[nt] = make_float4(0.f, 0.f, 0.f, 0.f);
#pragma unroll
        for (int ks = 0; ks < 4; ks++) {
            int kd = ks * 8;
#pragma unroll
            for (int nt = 0; nt < 8; nt++) {
                unsigned b0 = __float_as_uint(sm[(kd + tig) * 72 + nt * 8 + gid]);
                unsigned b1 = __float_as_uint(sm[(kd + tig + 4) * 72 + nt * 8 + gid]);
                mma_tf32(sc4[nt], qa[ks][0], qa[ks][1], qa[ks][2], qa[ks][3], b0, b1);
            }
        }

        // rel add + exp (no running max), accumulate row sums, store P
        int xk = tile * 2;
        float ehA0 = sm[AEH + qiA * 32 + xk];
        float ehA1 = sm[AEH + qiA * 32 + xk + 1];
        float ehB0 = sm[AEH + qiB * 32 + xk];
        float ehB1 = sm[AEH + qiB * 32 + xk + 1];
        float rsA = 0.f, rsB = 0.f;
#pragma unroll
        for (int nt = 0; nt < 8; nt++) {
            float ha = (nt < 4) ? ehA0 : ehA1;
            float hb = (nt < 4) ? ehB0 : ehB1;
            float px = __expf(sc4[nt].x + ewreg[0][(nt & 3) * 2 + 0] + ha);
            float py = __expf(sc4[nt].y + ewreg[0][(nt & 3) * 2 + 1] + ha);
            float pz = __expf(sc4[nt].z + ewreg[1][(nt & 3) * 2 + 0] + hb);
            float pw = __expf(sc4[nt].w + ewreg[1][(nt & 3) * 2 + 1] + hb);
            rsA += px + py; rsB += pz + pw;
            int cc = nt * 8 + 2 * tig;
            *(float2*)&sm[APO + qiA * 72 + cc] = make_float2(px, py);
            *(float2*)&sm[APO + qiB * 72 + cc] = make_float2(pz, pw);
        }
        sA += rsA; sB += rsB;
        __syncwarp();

        // O^T += V P^T
#pragma unroll
        for (int ks = 0; ks < 8; ks++) {
            int kk = ks * 8;
            unsigned p0[2], p1[2];
#pragma unroll
            for (int n2 = 0; n2 < 2; n2++) {
                p0[n2] = __float_as_uint(sm[APO + (qrow + n2 * 8 + gid) * 72 + kk + tig]);
                p1[n2] = __float_as_uint(sm[APO + (qrow + n2 * 8 + gid) * 72 + kk + tig + 4]);
            }
#pragma unroll
            for (int mt = 0; mt < 2; mt++) {
                int dv0 = mt * 16;
                unsigned a0 = __float_as_uint(sm[2304 + (dv0 + gid) * 72 + kk + tig]);
                unsigned a1 = __float_as_uint(sm[2304 + (dv0 + gid + 8) * 72 + kk + tig]);
                unsigned a2 = __float_as_uint(sm[2304 + (dv0 + gid) * 72 + kk + tig + 4]);
                unsigned a3 = __float_as_uint(sm[2304 + (dv0 + gid + 8) * 72 + kk + tig + 4]);
                mma_tf32(oc[mt][0], a0, a1, a2, a3, p0[0], p1[0]);
                mma_tf32(oc[mt][1], a0, a1, a2, a3, p0[1], p1[1]);
            }
        }

        __syncthreads();
        if (more) {
#pragma unroll
            for (int j = 0; j < 4; j++) {
                int fi = j * 128 + t, d = fi >> 4, c = (fi & 15) * 4;
                *(float4*)&sm[d * 72 + c]        = kr[j];
                *(float4*)&sm[2304 + d * 72 + c] = vr[j];
            }
        }
        __syncthreads();
    }

    // reduce row sums across tig lanes, broadcast 1/sum
    sA += __shfl_xor_sync(0xffffffffu, sA, 1);
    sA += __shfl_xor_sync(0xffffffffu, sA, 2);
    sB += __shfl_xor_sync(0xffffffffu, sB, 1);
    sB += __shfl_xor_sync(0xffffffffu, sB, 2);
    if (tig == 0) { sm[ASC + qiA] = 1.f / sA; sm[ASC + qiB] = 1.f / sB; }
    __syncwarp();
    float si[2][2];
#pragma unroll
    for (int n2 = 0; n2 < 2; n2++)
#pragma unroll
        for (int j = 0; j < 2; j++)
            si[n2][j] = sm[ASC + qrow + n2 * 8 + 2 * tig + j];
    float* ob = attn_out + ((long long)b * 256 + h * 32) * 1024 + q0;
#pragma unroll
    for (int mt = 0; mt < 2; mt++)
#pragma unroll
        for (int n2 = 0; n2 < 2; n2++) {
            int dv0 = mt * 16 + gid;
            int qq = qrow + n2 * 8 + 2 * tig;
            *(float2*)&ob[(long long)dv0 * 1024 + qq] =
                make_float2(oc[mt][n2].x * si[n2][0], oc[mt][n2].y * si[n2][1]);
            *(float2*)&ob[(long long)(dv0 + 8) * 1024 + qq] =
                make_float2(oc[mt][n2].z * si[n2][0], oc[mt][n2].w * si[n2][1]);
        }
}

// ---------------- launch: R9 schedule (conv on one side stream) ----------------
extern "C" void kernel_launch(void* const* d_in, const int* in_sizes, int n_in,
                              void* d_out, int out_size) {
    const float* x      = (const float*)d_in[0];
    const float* w_qkv  = (const float*)d_in[1];
    const float* b_qkv  = (const float*)d_in[2];
    const float* w_attn = (const float*)d_in[3];
    const float* b_attn = (const float*)d_in[4];
    const float* w_out  = (const float*)d_in[5];
    const float* b_out  = (const float*)d_in[6];
    const float* relw   = (const float*)d_in[7];
    const float* relh   = (const float*)d_in[8];
    float* out = (float*)d_out;

    float *qkv, *attn;
    cudaGetSymbolAddress((void**)&qkv,  g_qkv);
    cudaGetSymbolAddress((void**)&attn, g_attn);

    const int A_SMEM = A_SM_FLOATS * 4;   // 45312
    cudaFuncSetAttribute(attn_mma, cudaFuncAttributeMaxDynamicSharedMemorySize, A_SMEM);

    cudaStream_t s1;
    cudaEvent_t e0, e1;
    cudaStreamCreateWithFlags(&s1, cudaStreamNonBlocking);
    cudaEventCreateWithFlags(&e0, cudaEventDisableTiming);
    cudaEventCreateWithFlags(&e1, cudaEventDisableTiming);

    // fork: conv path on side stream
    cudaEventRecord(e0, 0);
    cudaStreamWaitEvent(s1, e0, 0);
    conv_gemm_tf32<<<dim3(8, 2, 8), 256, 0, s1>>>(w_out, x, out, b_out, 512LL * 1024);
    cudaEventRecord(e1, s1);

    // main chain on the capture stream
    sgemm_tf32<<<dim3(8, 6, 8), 256>>>(w_qkv, x, qkv, b_qkv,
                                       768, 1024, 256,
                                       256LL * 1024, 768LL * 1024, 0,
                                       0.17677669529663687f, 256);
    attn_mma<<<dim3(16, 64), 128, A_SMEM>>>(qkv, relw, relh, attn);
    sgemm_tf32<<<dim3(8, 2, 8), 256>>>(w_attn, attn, out, b_attn,
                                       256, 1024, 256,
                                       256LL * 1024, 512LL * 1024, 256,
                                       1.f, 0);

    // join
    cudaStreamWaitEvent(0, e1, 0);

    cudaStreamCaptureStatus st = cudaStreamCaptureStatusNone;
    cudaStreamIsCapturing(s1, &st);
    if (st == cudaStreamCaptureStatusNone) {
        cudaStreamDestroy(s1);
        cudaEventDestroy(e0);
        cudaEventDestroy(e1);
    }
}

// round 16
// speedup vs baseline: 1.1086x; 1.0718x over previous
#include <cuda_runtime.h>
#include <cstdint>

// ---------------- scratch ----------------
__device__ float g_qkv [8LL * 768 * 1024];
__device__ float g_attn[8LL * 256 * 1024];

__device__ __forceinline__ unsigned cvt_tf32(float x) {
    unsigned r;
    asm("cvt.rna.tf32.f32 %0, %1;" : "=r"(r) : "f"(x));
    return r;
}
__device__ __forceinline__ void mma_tf32(float4& c, unsigned a0, unsigned a1,
                                         unsigned a2, unsigned a3,
                                         unsigned b0, unsigned b1) {
    asm volatile(
        "mma.sync.aligned.m16n8k8.row.col.f32.tf32.tf32.f32 "
        "{%0,%1,%2,%3}, {%4,%5,%6,%7}, {%8,%9}, {%0,%1,%2,%3};"
        : "+f"(c.x), "+f"(c.y), "+f"(c.z), "+f"(c.w)
        : "r"(a0), "r"(a1), "r"(a2), "r"(a3), "r"(b0), "r"(b1));
}

// ---------------- tf32 GEMM: 128x128 tile, BK=32, 8 warps, reg prefetch ----------------
__global__ __launch_bounds__(256) void sgemm_tf32(
    const float* __restrict__ A, const float* __restrict__ X,
    float* __restrict__ C, const float* __restrict__ bias,
    int M, int N, int K, long long sX, long long sC, int crow,
    float qscale, int qrows)
{
    __shared__ float As[32 * 136];
    __shared__ float Bs[32 * 136];
    const int bz = blockIdx.z;
    const float* Xb = X + (long long)bz * sX;
    float* Cb = C + (long long)bz * sC;
    const int row0 = blockIdx.y * 128, col0 = blockIdx.x * 128;
    const int t = threadIdx.x;
    const int wid = t >> 5, lane = t & 31;
    const int gid = lane >> 2, tig = lane & 3;
    const int wm = wid >> 1, wn = wid & 1;
    const int ar = t >> 1, aks = (t & 1) * 16;
    const int br = t >> 3, bc = (t & 7) * 4;
    const float* Ap = A + (long long)(row0 + ar) * K + aks;
    const float* Xp = Xb + (long long)br * N + col0 + bc;

    float4 pa[4], pb[4];
#pragma unroll
    for (int j = 0; j < 4; j++) {
        pa[j] = *(const float4*)(Ap + 4 * j);
        pb[j] = *(const float4*)(Xp + 32 * j);
    }
    float4 acc[2][8];
#pragma unroll
    for (int mt = 0; mt < 2; mt++)
#pragma unroll
        for (int nt = 0; nt < 8; nt++) acc[mt][nt] = make_float4(0.f, 0.f, 0.f, 0.f);

    for (int k0 = 0;; ) {
#pragma unroll
        for (int j = 0; j < 4; j++) {
            As[(aks + 4 * j + 0) * 136 + ar] = __uint_as_float(cvt_tf32(pa[j].x));
            As[(aks + 4 * j + 1) * 136 + ar] = __uint_as_float(cvt_tf32(pa[j].y));
            As[(aks + 4 * j + 2) * 136 + ar] = __uint_as_float(cvt_tf32(pa[j].z));
            As[(aks + 4 * j + 3) * 136 + ar] = __uint_as_float(cvt_tf32(pa[j].w));
            float4 bb;
            bb.x = __uint_as_float(cvt_tf32(pb[j].x));
            bb.y = __uint_as_float(cvt_tf32(pb[j].y));
            bb.z = __uint_as_float(cvt_tf32(pb[j].z));
            bb.w = __uint_as_float(cvt_tf32(pb[j].w));
            *(float4*)&Bs[br * 136 + bc + 32 * j] = bb;
        }
        __syncthreads();
        bool last = (k0 + 32 >= K);
        if (!last) {
#pragma unroll
            for (int j = 0; j < 4; j++) {
                pa[j] = *(const float4*)(Ap + k0 + 32 + 4 * j);
                pb[j] = *(const float4*)(Xp + (long long)(k0 + 32) * N + 32 * j);
            }
        }
#pragma unroll
        for (int ks = 0; ks < 4; ks++) {
            const int kk = ks * 8;
            unsigned a[2][4];
#pragma unroll
            for (int mt = 0; mt < 2; mt++) {
                int m0 = wm * 32 + mt * 16;
                a[mt][0] = __float_as_uint(As[(kk + tig) * 136 + m0 + gid]);
                a[mt][1] = __float_as_uint(As[(kk + tig) * 136 + m0 + gid + 8]);
                a[mt][2] = __float_as_uint(As[(kk + tig + 4) * 136 + m0 + gid]);
                a[mt][3] = __float_as_uint(As[(kk + tig + 4) * 136 + m0 + gid + 8]);
            }
#pragma unroll
            for (int nt = 0; nt < 8; nt++) {
                int n0 = wn * 64 + nt * 8;
                unsigned b0 = __float_as_uint(Bs[(kk + tig) * 136 + n0 + gid]);
                unsigned b1 = __float_as_uint(Bs[(kk + tig + 4) * 136 + n0 + gid]);
                mma_tf32(acc[0][nt], a[0][0], a[0][1], a[0][2], a[0][3], b0, b1);
                mma_tf32(acc[1][nt], a[1][0], a[1][1], a[1][2], a[1][3], b0, b1);
            }
        }
        __syncthreads();
        k0 += 32;
        if (last) break;
    }
#pragma unroll
    for (int mt = 0; mt < 2; mt++) {
        int rA = row0 + wm * 32 + mt * 16 + gid;
        int rB = rA + 8;
        float bA = bias ? bias[rA] : 0.f, bB = bias ? bias[rB] : 0.f;
        float sA = (rA < qrows) ? qscale : 1.f, sB = (rB < qrows) ? qscale : 1.f;
#pragma unroll
        for (int nt = 0; nt < 8; nt++) {
            int cc = col0 + wn * 64 + nt * 8 + 2 * tig;
            *(float2*)&Cb[(long long)(crow + rA) * N + cc] =
                make_float2((acc[mt][nt].x + bA) * sA, (acc[mt][nt].y + bA) * sA);
            *(float2*)&Cb[(long long)(crow + rB) * N + cc] =
                make_float2((acc[mt][nt].z + bB) * sB, (acc[mt][nt].w + bB) * sB);
        }
    }
}

// ---------------- implicit-im2col conv GEMM (3x3 pad1 on 32x32), 128x128 tile ----------------
__global__ __launch_bounds__(256) void conv_gemm_tf32(
    const float* __restrict__ A, const float* __restrict__ x,
    float* __restrict__ C, const float* __restrict__ bias,
    long long sC)
{
    const int N = 1024, K = 2304;
    __shared__ float As[32 * 136];
    __shared__ float Bs[32 * 136];
    const int bz = blockIdx.z;
    const float* Xb = x + (long long)bz * 256 * 1024;
    float* Cb = C + (long long)bz * sC;
    const int row0 = blockIdx.y * 128, col0 = blockIdx.x * 128;
    const int t = threadIdx.x;
    const int wid = t >> 5, lane = t & 31;
    const int gid = lane >> 2, tig = lane & 3;
    const int wm = wid >> 1, wn = wid & 1;
    const int ar = t >> 1, aks = (t & 1) * 16;
    const int br = t >> 3, bc = (t & 7) * 4;
    const float* Ap = A + (long long)(row0 + ar) * K + aks;

    float4 pa[4];
    float pbv[16];
#pragma unroll
    for (int j = 0; j < 4; j++) pa[j] = *(const float4*)(Ap + 4 * j);

    auto loadB = [&](int k0) {
        int k = k0 + br;
        int ci = k / 9, r = k - 9 * ci;
        int kh = r / 3, kw = r - 3 * kh;
        const float* xp = Xb + (long long)ci * 1024 + (kh - 1) * 32 + (kw - 1);
#pragma unroll
        for (int j = 0; j < 4; j++) {
#pragma unroll
            for (int i = 0; i < 4; i++) {
                int n = col0 + bc + 32 * j + i;
                int y = n >> 5, xx = n & 31;
                bool ok = (y + kh >= 1) && (y + kh <= 32) && (xx + kw >= 1) && (xx + kw <= 32);
                pbv[j * 4 + i] = ok ? xp[n] : 0.f;
            }
        }
    };
    loadB(0);

    float4 acc[2][8];
#pragma unroll
    for (int mt = 0; mt < 2; mt++)
#pragma unroll
        for (int nt = 0; nt < 8; nt++) acc[mt][nt] = make_float4(0.f, 0.f, 0.f, 0.f);

    for (int k0 = 0;; ) {
#pragma unroll
        for (int j = 0; j < 4; j++) {
            As[(aks + 4 * j + 0) * 136 + ar] = __uint_as_float(cvt_tf32(pa[j].x));
            As[(aks + 4 * j + 1) * 136 + ar] = __uint_as_float(cvt_tf32(pa[j].y));
            As[(aks + 4 * j + 2) * 136 + ar] = __uint_as_float(cvt_tf32(pa[j].z));
            As[(aks + 4 * j + 3) * 136 + ar] = __uint_as_float(cvt_tf32(pa[j].w));
            float4 bb;
            bb.x = __uint_as_float(cvt_tf32(pbv[j * 4 + 0]));
            bb.y = __uint_as_float(cvt_tf32(pbv[j * 4 + 1]));
            bb.z = __uint_as_float(cvt_tf32(pbv[j * 4 + 2]));
            bb.w = __uint_as_float(cvt_tf32(pbv[j * 4 + 3]));
            *(float4*)&Bs[br * 136 + bc + 32 * j] = bb;
        }
        __syncthreads();
        bool last = (k0 + 32 >= K);
        if (!last) {
#pragma unroll
            for (int j = 0; j < 4; j++) pa[j] = *(const float4*)(Ap + k0 + 32 + 4 * j);
            loadB(k0 + 32);
        }
#pragma unroll
        for (int ks = 0; ks < 4; ks++) {
            const int kk = ks * 8;
            unsigned a[2][4];
#pragma unroll
            for (int mt = 0; mt < 2; mt++) {
                int m0 = wm * 32 + mt * 16;
                a[mt][0] = __float_as_uint(As[(kk + tig) * 136 + m0 + gid]);
                a[mt][1] = __float_as_uint(As[(kk + tig) * 136 + m0 + gid + 8]);
                a[mt][2] = __float_as_uint(As[(kk + tig + 4) * 136 + m0 + gid]);
                a[mt][3] = __float_as_uint(As[(kk + tig + 4) * 136 + m0 + gid + 8]);
            }
#pragma unroll
            for (int nt = 0; nt < 8; nt++) {
                int n0 = wn * 64 + nt * 8;
                unsigned b0 = __float_as_uint(Bs[(kk + tig) * 136 + n0 + gid]);
                unsigned b1 = __float_as_uint(Bs[(kk + tig + 4) * 136 + n0 + gid]);
                mma_tf32(acc[0][nt], a[0][0], a[0][1], a[0][2], a[0][3], b0, b1);
                mma_tf32(acc[1][nt], a[1][0], a[1][1], a[1][2], a[1][3], b0, b1);
            }
        }
        __syncthreads();
        k0 += 32;
        if (last) break;
    }
#pragma unroll
    for (int mt = 0; mt < 2; mt++) {
        int rA = row0 + wm * 32 + mt * 16 + gid;
        int rB = rA + 8;
        float bA = bias[rA], bB = bias[rB];
#pragma unroll
        for (int nt = 0; nt < 8; nt++) {
            int cc = col0 + wn * 64 + nt * 8 + 2 * tig;
            *(float2*)&Cb[(long long)rA * N + cc] =
                make_float2(acc[mt][nt].x + bA, acc[mt][nt].y + bA);
            *(float2*)&Cb[(long long)rB * N + cc] =
                make_float2(acc[mt][nt].z + bB, acc[mt][nt].w + bB);
        }
    }
}

// ---------------- flash attention: fixed-max softmax, 2 (b,h) pairs per block ----------------
#define APO  4608
#define AEH  9216
#define ASC  11264
#define A_SM_FLOATS 11328

__global__ __launch_bounds__(128) void attn_mma(
    const float* __restrict__ qkv,
    const float* __restrict__ relw,   // [63][32]
    const float* __restrict__ relh,   // [63][32]
    float* __restrict__ attn_out)     // [B][256][1024]
{
    extern __shared__ float sm[];
    const int bx = blockIdx.x;
    const int q0 = bx * 64;
    const int t = threadIdx.x;
    const int wid = t >> 5, lane = t & 31;
    const int gid = lane >> 2, tig = lane & 3;
    const int qrow = wid * 16;
    const int qiA = qrow + gid, qiB = qiA + 8;

    for (int rep = 0; rep < 2; rep++) {
        const int bh = blockIdx.y * 2 + rep;
        const int b = bh >> 3, h = bh & 7;

        const float* qb = qkv + ((long long)b * 768 +       h * 32) * 1024;
        const float* kb = qkv + ((long long)b * 768 + 256 + h * 32) * 1024;
        const float* vb = qkv + ((long long)b * 768 + 512 + h * 32) * 1024;

        // prologue: Q [q][36] in KV region; rel tables stride 36 in P region
        for (int i = t; i < 2048; i += 128) {
            int d = i >> 6, qi = i & 63;
            sm[qi * 36 + d] = qb[d * 1024 + q0 + qi];
        }
        for (int i = t; i < 2016; i += 128) {
            int m = i >> 5, d = i & 31;
            sm[APO + m * 36 + d]        = relw[i];
            sm[APO + 2268 + m * 36 + d] = relh[i];
        }
        __syncthreads();

        // eh2[qi][xk] = eh[qi][xk - hq(qi) + 31]
        for (int e = t; e < 2048; e += 128) {
            int qi = e >> 5, xk = e & 31;
            int m = xk - (2 * bx + (qi >> 5)) + 31;
            const float* qp = sm + qi * 36;
            const float* rp = sm + APO + 2268 + m * 36;
            float s = 0.f;
#pragma unroll
            for (int d = 0; d < 32; d += 4) {
                float4 q4 = *(const float4*)(qp + d);
                float4 r4 = *(const float4*)(rp + d);
                s += q4.x * r4.x + q4.y * r4.y + q4.z * r4.z + q4.w * r4.w;
            }
            sm[AEH + e] = s;
        }

        unsigned qa[4][4];
#pragma unroll
        for (int ks = 0; ks < 4; ks++) {
            int kd = ks * 8;
            qa[ks][0] = cvt_tf32(sm[qiA * 36 + kd + tig]);
            qa[ks][1] = cvt_tf32(sm[qiB * 36 + kd + tig]);
            qa[ks][2] = cvt_tf32(sm[qiA * 36 + kd + tig + 4]);
            qa[ks][3] = cvt_tf32(sm[qiB * 36 + kd + tig + 4]);
        }
        float ewreg[2][8];
#pragma unroll
        for (int rr = 0; rr < 2; rr++) {
            int qi = rr ? qiB : qiA;
            const float* qp = sm + qi * 36;
#pragma unroll
            for (int e = 0; e < 8; e++) {
                int yk = (e >> 1) * 8 + tig * 2 + (e & 1);
                int m = yk - (qi & 31) + 31;
                const float* rp = sm + APO + m * 36;
                float s = 0.f;
#pragma unroll
                for (int d = 0; d < 32; d += 4) {
                    float4 q4 = *(const float4*)(qp + d);
                    float4 r4 = *(const float4*)(rp + d);
                    s += q4.x * r4.x + q4.y * r4.y + q4.z * r4.z + q4.w * r4.w;
                }
                ewreg[rr][e] = s;
            }
        }
        __syncthreads();

        // stage tile 0
        {
            float4 kr0[4], vr0[4];
#pragma unroll
            for (int j = 0; j < 4; j++) {
                int fi = j * 128 + t, d = fi >> 4, c = (fi & 15) * 4;
                kr0[j] = *(const float4*)(kb + d * 1024 + c);
                vr0[j] = *(const float4*)(vb + d * 1024 + c);
            }
#pragma unroll
            for (int j = 0; j < 4; j++) {
                int fi = j * 128 + t, d = fi >> 4, c = (fi & 15) * 4;
                *(float4*)&sm[d * 72 + c]        = kr0[j];
                *(float4*)&sm[2304 + d * 72 + c] = vr0[j];
            }
        }
        __syncthreads();

        float sA = 0.f, sB = 0.f;
        float4 oc[2][2];
#pragma unroll
        for (int mt = 0; mt < 2; mt++)
#pragma unroll
            for (int n2 = 0; n2 < 2; n2++) oc[mt][n2] = make_float4(0.f, 0.f, 0.f, 0.f);

        float4 kr[4], vr[4];
        for (int tile = 0; tile < 16; tile++) {
            const bool more = (tile < 15);
            if (more) {
                int k0n = (tile + 1) * 64;
#pragma unroll
                for (int j = 0; j < 4; j++) {
                    int fi = j * 128 + t, d = fi >> 4, c = (fi & 15) * 4;
                    kr[j] = *(const float4*)(kb + d * 1024 + k0n + c);
                    vr[j] = *(const float4*)(vb + d * 1024 + k0n + c);
                }
            }

            float4 sc4[8];
#pragma unroll
            for (int nt = 0; nt < 8; nt++) sc4[nt] = make_float4(0.f, 0.f, 0.f, 0.f);
#pragma unroll
            for (int ks = 0; ks < 4; ks++) {
                int kd = ks * 8;
#pragma unroll
                for (int nt = 0; nt < 8; nt++) {
                    unsigned b0 = __float_as_uint(sm[(kd + tig) * 72 + nt * 8 + gid]);
                    unsigned b1 = __float_as_uint(sm[(kd + tig + 4) * 72 + nt * 8 + gid]);
                    mma_tf32(sc4[nt], qa[ks][0], qa[ks][1], qa[ks][2], qa[ks][3], b0, b1);
                }
            }

            int xk = tile * 2;
            float ehA0 = sm[AEH + qiA * 32 + xk];
            float ehA1 = sm[AEH + qiA * 32 + xk + 1];
            float ehB0 = sm[AEH + qiB * 32 + xk];
            float ehB1 = sm[AEH + qiB * 32 + xk + 1];
            float rsA = 0.f, rsB = 0.f;
#pragma unroll
            for (int nt = 0; nt < 8; nt++) {
                float ha = (nt < 4) ? ehA0 : ehA1;
                float hb = (nt < 4) ? ehB0 : ehB1;
                float px = __expf(sc4[nt].x + ewreg[0][(nt & 3) * 2 + 0] + ha);
                float py = __expf(sc4[nt].y + ewreg[0][(nt & 3) * 2 + 1] + ha);
                float pz = __expf(sc4[nt].z + ewreg[1][(nt & 3) * 2 + 0] + hb);
                float pw = __expf(sc4[nt].w + ewreg[1][(nt & 3) * 2 + 1] + hb);
                rsA += px + py; rsB += pz + pw;
                int cc = nt * 8 + 2 * tig;
                *(float2*)&sm[APO + qiA * 72 + cc] = make_float2(px, py);
                *(float2*)&sm[APO + qiB * 72 + cc] = make_float2(pz, pw);
            }
            sA += rsA; sB += rsB;
            __syncwarp();

#pragma unroll
            for (int ks = 0; ks < 8; ks++) {
                int kk = ks * 8;
                unsigned p0[2], p1[2];
#pragma unroll
                for (int n2 = 0; n2 < 2; n2++) {
                    p0[n2] = __float_as_uint(sm[APO + (qrow + n2 * 8 + gid) * 72 + kk + tig]);
                    p1[n2] = __float_as_uint(sm[APO + (qrow + n2 * 8 + gid) * 72 + kk + tig + 4]);
                }
#pragma unroll
                for (int mt = 0; mt < 2; mt++) {
                    int dv0 = mt * 16;
                    unsigned a0 = __float_as_uint(sm[2304 + (dv0 + gid) * 72 + kk + tig]);
                    unsigned a1 = __float_as_uint(sm[2304 + (dv0 + gid + 8) * 72 + kk + tig]);
                    unsigned a2 = __float_as_uint(sm[2304 + (dv0 + gid) * 72 + kk + tig + 4]);
                    unsigned a3 = __float_as_uint(sm[2304 + (dv0 + gid + 8) * 72 + kk + tig + 4]);
                    mma_tf32(oc[mt][0], a0, a1, a2, a3, p0[0], p1[0]);
                    mma_tf32(oc[mt][1], a0, a1, a2, a3, p0[1], p1[1]);
                }
            }

            __syncthreads();
            if (more) {
#pragma unroll
                for (int j = 0; j < 4; j++) {
                    int fi = j * 128 + t, d = fi >> 4, c = (fi & 15) * 4;
                    *(float4*)&sm[d * 72 + c]        = kr[j];
                    *(float4*)&sm[2304 + d * 72 + c] = vr[j];
                }
            }
            __syncthreads();
        }

        sA += __shfl_xor_sync(0xffffffffu, sA, 1);
        sA += __shfl_xor_sync(0xffffffffu, sA, 2);
        sB += __shfl_xor_sync(0xffffffffu, sB, 1);
        sB += __shfl_xor_sync(0xffffffffu, sB, 2);
        if (tig == 0) { sm[ASC + qiA] = 1.f / sA; sm[ASC + qiB] = 1.f / sB; }
        __syncwarp();
        float si[2][2];
#pragma unroll
        for (int n2 = 0; n2 < 2; n2++)
#pragma unroll
            for (int j = 0; j < 2; j++)
                si[n2][j] = sm[ASC + qrow + n2 * 8 + 2 * tig + j];
        float* ob = attn_out + ((long long)b * 256 + h * 32) * 1024 + q0;
#pragma unroll
        for (int mt = 0; mt < 2; mt++)
#pragma unroll
            for (int n2 = 0; n2 < 2; n2++) {
                int dv0 = mt * 16 + gid;
                int qq = qrow + n2 * 8 + 2 * tig;
                *(float2*)&ob[(long long)dv0 * 1024 + qq] =
                    make_float2(oc[mt][n2].x * si[n2][0], oc[mt][n2].y * si[n2][1]);
                *(float2*)&ob[(long long)(dv0 + 8) * 1024 + qq] =
                    make_float2(oc[mt][n2].z * si[n2][0], oc[mt][n2].w * si[n2][1]);
            }
        __syncthreads();   // all reads of this rep's smem done before next rep overwrites
    }
}

// ---------------- launch: R9 schedule (conv on one side stream) ----------------
extern "C" void kernel_launch(void* const* d_in, const int* in_sizes, int n_in,
                              void* d_out, int out_size) {
    const float* x      = (const float*)d_in[0];
    const float* w_qkv  = (const float*)d_in[1];
    const float* b_qkv  = (const float*)d_in[2];
    const float* w_attn = (const float*)d_in[3];
    const float* b_attn = (const float*)d_in[4];
    const float* w_out  = (const float*)d_in[5];
    const float* b_out  = (const float*)d_in[6];
    const float* relw   = (const float*)d_in[7];
    const float* relh   = (const float*)d_in[8];
    float* out = (float*)d_out;

    float *qkv, *attn;
    cudaGetSymbolAddress((void**)&qkv,  g_qkv);
    cudaGetSymbolAddress((void**)&attn, g_attn);

    const int A_SMEM = A_SM_FLOATS * 4;   // 45312
    cudaFuncSetAttribute(attn_mma, cudaFuncAttributeMaxDynamicSharedMemorySize, A_SMEM);

    cudaStream_t s1;
    cudaEvent_t e0, e1;
    cudaStreamCreateWithFlags(&s1, cudaStreamNonBlocking);
    cudaEventCreateWithFlags(&e0, cudaEventDisableTiming);
    cudaEventCreateWithFlags(&e1, cudaEventDisableTiming);

    // fork: conv path on side stream
    cudaEventRecord(e0, 0);
    cudaStreamWaitEvent(s1, e0, 0);
    conv_gemm_tf32<<<dim3(8, 2, 8), 256, 0, s1>>>(w_out, x, out, b_out, 512LL * 1024);
    cudaEventRecord(e1, s1);

    // main chain on the capture stream
    sgemm_tf32<<<dim3(8, 6, 8), 256>>>(w_qkv, x, qkv, b_qkv,
                                       768, 1024, 256,
                                       256LL * 1024, 768LL * 1024, 0,
                                       0.17677669529663687f, 256);
    attn_mma<<<dim3(16, 32), 128, A_SMEM>>>(qkv, relw, relh, attn);
    sgemm_tf32<<<dim3(8, 2, 8), 256>>>(w_attn, attn, out, b_attn,
                                       256, 1024, 256,
                                       256LL * 1024, 512LL * 1024, 256,
                                       1.f, 0);

    // join
    cudaStreamWaitEvent(0, e1, 0);

    cudaStreamCaptureStatus st = cudaStreamCaptureStatusNone;
    cudaStreamIsCapturing(s1, &st);
    if (st == cudaStreamCaptureStatusNone) {
        cudaStreamDestroy(s1);
        cudaEventDestroy(e0);
        cudaEventDestroy(e1);
    }
}

// round 17
// speedup vs baseline: 1.1861x; 1.0699x over previous
#include <cuda_runtime.h>
#include <cstdint>

// ---------------- scratch ----------------
__device__ float g_qkv [8LL * 768 * 1024];
__device__ float g_attn[8LL * 256 * 1024];

__device__ __forceinline__ unsigned cvt_tf32(float x) {
    unsigned r;
    asm("cvt.rna.tf32.f32 %0, %1;" : "=r"(r) : "f"(x));
    return r;
}
__device__ __forceinline__ void mma_tf32(float4& c, unsigned a0, unsigned a1,
                                         unsigned a2, unsigned a3,
                                         unsigned b0, unsigned b1) {
    asm volatile(
        "mma.sync.aligned.m16n8k8.row.col.f32.tf32.tf32.f32 "
        "{%0,%1,%2,%3}, {%4,%5,%6,%7}, {%8,%9}, {%0,%1,%2,%3};"
        : "+f"(c.x), "+f"(c.y), "+f"(c.z), "+f"(c.w)
        : "r"(a0), "r"(a1), "r"(a2), "r"(a3), "r"(b0), "r"(b1));
}

// ---------------- tf32 GEMM: 128x128 tile, BK=32, 8 warps, reg prefetch ----------------
__global__ __launch_bounds__(256) void sgemm_tf32(
    const float* __restrict__ A, const float* __restrict__ X,
    float* __restrict__ C, const float* __restrict__ bias,
    int M, int N, int K, long long sX, long long sC, int crow,
    float qscale, int qrows)
{
    __shared__ float As[32 * 136];
    __shared__ float Bs[32 * 136];
    const int bz = blockIdx.z;
    const float* Xb = X + (long long)bz * sX;
    float* Cb = C + (long long)bz * sC;
    const int row0 = blockIdx.y * 128, col0 = blockIdx.x * 128;
    const int t = threadIdx.x;
    const int wid = t >> 5, lane = t & 31;
    const int gid = lane >> 2, tig = lane & 3;
    const int wm = wid >> 1, wn = wid & 1;
    const int ar = t >> 1, aks = (t & 1) * 16;
    const int br = t >> 3, bc = (t & 7) * 4;
    const float* Ap = A + (long long)(row0 + ar) * K + aks;
    const float* Xp = Xb + (long long)br * N + col0 + bc;

    float4 pa[4], pb[4];
#pragma unroll
    for (int j = 0; j < 4; j++) {
        pa[j] = *(const float4*)(Ap + 4 * j);
        pb[j] = *(const float4*)(Xp + 32 * j);
    }
    float4 acc[2][8];
#pragma unroll
    for (int mt = 0; mt < 2; mt++)
#pragma unroll
        for (int nt = 0; nt < 8; nt++) acc[mt][nt] = make_float4(0.f, 0.f, 0.f, 0.f);

    for (int k0 = 0;; ) {
#pragma unroll
        for (int j = 0; j < 4; j++) {
            As[(aks + 4 * j + 0) * 136 + ar] = __uint_as_float(cvt_tf32(pa[j].x));
            As[(aks + 4 * j + 1) * 136 + ar] = __uint_as_float(cvt_tf32(pa[j].y));
            As[(aks + 4 * j + 2) * 136 + ar] = __uint_as_float(cvt_tf32(pa[j].z));
            As[(aks + 4 * j + 3) * 136 + ar] = __uint_as_float(cvt_tf32(pa[j].w));
            float4 bb;
            bb.x = __uint_as_float(cvt_tf32(pb[j].x));
            bb.y = __uint_as_float(cvt_tf32(pb[j].y));
            bb.z = __uint_as_float(cvt_tf32(pb[j].z));
            bb.w = __uint_as_float(cvt_tf32(pb[j].w));
            *(float4*)&Bs[br * 136 + bc + 32 * j] = bb;
        }
        __syncthreads();
        bool last = (k0 + 32 >= K);
        if (!last) {
#pragma unroll
            for (int j = 0; j < 4; j++) {
                pa[j] = *(const float4*)(Ap + k0 + 32 + 4 * j);
                pb[j] = *(const float4*)(Xp + (long long)(k0 + 32) * N + 32 * j);
            }
        }
#pragma unroll
        for (int ks = 0; ks < 4; ks++) {
            const int kk = ks * 8;
            unsigned a[2][4];
#pragma unroll
            for (int mt = 0; mt < 2; mt++) {
                int m0 = wm * 32 + mt * 16;
                a[mt][0] = __float_as_uint(As[(kk + tig) * 136 + m0 + gid]);
                a[mt][1] = __float_as_uint(As[(kk + tig) * 136 + m0 + gid + 8]);
                a[mt][2] = __float_as_uint(As[(kk + tig + 4) * 136 + m0 + gid]);
                a[mt][3] = __float_as_uint(As[(kk + tig + 4) * 136 + m0 + gid + 8]);
            }
#pragma unroll
            for (int nt = 0; nt < 8; nt++) {
                int n0 = wn * 64 + nt * 8;
                unsigned b0 = __float_as_uint(Bs[(kk + tig) * 136 + n0 + gid]);
                unsigned b1 = __float_as_uint(Bs[(kk + tig + 4) * 136 + n0 + gid]);
                mma_tf32(acc[0][nt], a[0][0], a[0][1], a[0][2], a[0][3], b0, b1);
                mma_tf32(acc[1][nt], a[1][0], a[1][1], a[1][2], a[1][3], b0, b1);
            }
        }
        __syncthreads();
        k0 += 32;
        if (last) break;
    }
#pragma unroll
    for (int mt = 0; mt < 2; mt++) {
        int rA = row0 + wm * 32 + mt * 16 + gid;
        int rB = rA + 8;
        float bA = bias ? bias[rA] : 0.f, bB = bias ? bias[rB] : 0.f;
        float sA = (rA < qrows) ? qscale : 1.f, sB = (rB < qrows) ? qscale : 1.f;
#pragma unroll
        for (int nt = 0; nt < 8; nt++) {
            int cc = col0 + wn * 64 + nt * 8 + 2 * tig;
            *(float2*)&Cb[(long long)(crow + rA) * N + cc] =
                make_float2((acc[mt][nt].x + bA) * sA, (acc[mt][nt].y + bA) * sA);
            *(float2*)&Cb[(long long)(crow + rB) * N + cc] =
                make_float2((acc[mt][nt].z + bB) * sB, (acc[mt][nt].w + bB) * sB);
        }
    }
}

// ---------------- implicit-im2col conv GEMM (3x3 pad1 on 32x32), 128x128 tile ----------------
__global__ __launch_bounds__(256) void conv_gemm_tf32(
    const float* __restrict__ A, const float* __restrict__ x,
    float* __restrict__ C, const float* __restrict__ bias,
    long long sC)
{
    const int N = 1024, K = 2304;
    __shared__ float As[32 * 136];
    __shared__ float Bs[32 * 136];
    const int bz = blockIdx.z;
    const float* Xb = x + (long long)bz * 256 * 1024;
    float* Cb = C + (long long)bz * sC;
    const int row0 = blockIdx.y * 128, col0 = blockIdx.x * 128;
    const int t = threadIdx.x;
    const int wid = t >> 5, lane = t & 31;
    const int gid = lane >> 2, tig = lane & 3;
    const int wm = wid >> 1, wn = wid & 1;
    const int ar = t >> 1, aks = (t & 1) * 16;
    const int br = t >> 3, bc = (t & 7) * 4;
    const float* Ap = A + (long long)(row0 + ar) * K + aks;

    float4 pa[4];
    float pbv[16];
#pragma unroll
    for (int j = 0; j < 4; j++) pa[j] = *(const float4*)(Ap + 4 * j);

    auto loadB = [&](int k0) {
        int k = k0 + br;
        int ci = k / 9, r = k - 9 * ci;
        int kh = r / 3, kw = r - 3 * kh;
        const float* xp = Xb + (long long)ci * 1024 + (kh - 1) * 32 + (kw - 1);
#pragma unroll
        for (int j = 0; j < 4; j++) {
#pragma unroll
            for (int i = 0; i < 4; i++) {
                int n = col0 + bc + 32 * j + i;
                int y = n >> 5, xx = n & 31;
                bool ok = (y + kh >= 1) && (y + kh <= 32) && (xx + kw >= 1) && (xx + kw <= 32);
                pbv[j * 4 + i] = ok ? xp[n] : 0.f;
            }
        }
    };
    loadB(0);

    float4 acc[2][8];
#pragma unroll
    for (int mt = 0; mt < 2; mt++)
#pragma unroll
        for (int nt = 0; nt < 8; nt++) acc[mt][nt] = make_float4(0.f, 0.f, 0.f, 0.f);

    for (int k0 = 0;; ) {
#pragma unroll
        for (int j = 0; j < 4; j++) {
            As[(aks + 4 * j + 0) * 136 + ar] = __uint_as_float(cvt_tf32(pa[j].x));
            As[(aks + 4 * j + 1) * 136 + ar] = __uint_as_float(cvt_tf32(pa[j].y));
            As[(aks + 4 * j + 2) * 136 + ar] = __uint_as_float(cvt_tf32(pa[j].z));
            As[(aks + 4 * j + 3) * 136 + ar] = __uint_as_float(cvt_tf32(pa[j].w));
            float4 bb;
            bb.x = __uint_as_float(cvt_tf32(pbv[j * 4 + 0]));
            bb.y = __uint_as_float(cvt_tf32(pbv[j * 4 + 1]));
            bb.z = __uint_as_float(cvt_tf32(pbv[j * 4 + 2]));
            bb.w = __uint_as_float(cvt_tf32(pbv[j * 4 + 3]));
            *(float4*)&Bs[br * 136 + bc + 32 * j] = bb;
        }
        __syncthreads();
        bool last = (k0 + 32 >= K);
        if (!last) {
#pragma unroll
            for (int j = 0; j < 4; j++) pa[j] = *(const float4*)(Ap + k0 + 32 + 4 * j);
            loadB(k0 + 32);
        }
#pragma unroll
        for (int ks = 0; ks < 4; ks++) {
            const int kk = ks * 8;
            unsigned a[2][4];
#pragma unroll
            for (int mt = 0; mt < 2; mt++) {
                int m0 = wm * 32 + mt * 16;
                a[mt][0] = __float_as_uint(As[(kk + tig) * 136 + m0 + gid]);
                a[mt][1] = __float_as_uint(As[(kk + tig) * 136 + m0 + gid + 8]);
                a[mt][2] = __float_as_uint(As[(kk + tig + 4) * 136 + m0 + gid]);
                a[mt][3] = __float_as_uint(As[(kk + tig + 4) * 136 + m0 + gid + 8]);
            }
#pragma unroll
            for (int nt = 0; nt < 8; nt++) {
                int n0 = wn * 64 + nt * 8;
                unsigned b0 = __float_as_uint(Bs[(kk + tig) * 136 + n0 + gid]);
                unsigned b1 = __float_as_uint(Bs[(kk + tig + 4) * 136 + n0 + gid]);
                mma_tf32(acc[0][nt], a[0][0], a[0][1], a[0][2], a[0][3], b0, b1);
                mma_tf32(acc[1][nt], a[1][0], a[1][1], a[1][2], a[1][3], b0, b1);
            }
        }
        __syncthreads();
        k0 += 32;
        if (last) break;
    }
#pragma unroll
    for (int mt = 0; mt < 2; mt++) {
        int rA = row0 + wm * 32 + mt * 16 + gid;
        int rB = rA + 8;
        float bA = bias[rA], bB = bias[rB];
#pragma unroll
        for (int nt = 0; nt < 8; nt++) {
            int cc = col0 + wn * 64 + nt * 8 + 2 * tig;
            *(float2*)&Cb[(long long)rA * N + cc] =
                make_float2(acc[mt][nt].x + bA, acc[mt][nt].y + bA);
            *(float2*)&Cb[(long long)rB * N + cc] =
                make_float2(acc[mt][nt].z + bB, acc[mt][nt].w + bB);
        }
    }
}

// ---------------- tensor-core flash attention, fixed-max softmax (R13 best) ----------------
#define APO  4608
#define AEH  9216
#define ASC  11264
#define A_SM_FLOATS 11328

__global__ __launch_bounds__(128) void attn_mma(
    const float* __restrict__ qkv,
    const float* __restrict__ relw,   // [63][32]
    const float* __restrict__ relh,   // [63][32]
    float* __restrict__ attn_out)     // [B][256][1024]
{
    extern __shared__ float sm[];
    const int bh = blockIdx.y;
    const int b = bh >> 3, h = bh & 7;
    const int bx = blockIdx.x;
    const int q0 = bx * 64;
    const int t = threadIdx.x;
    const int wid = t >> 5, lane = t & 31;
    const int gid = lane >> 2, tig = lane & 3;
    const int qrow = wid * 16;

    const float* qb = qkv + ((long long)b * 768 +       h * 32) * 1024;
    const float* kb = qkv + ((long long)b * 768 + 256 + h * 32) * 1024;
    const float* vb = qkv + ((long long)b * 768 + 512 + h * 32) * 1024;

    for (int i = t; i < 2048; i += 128) {
        int d = i >> 6, qi = i & 63;
        sm[qi * 36 + d] = qb[d * 1024 + q0 + qi];
    }
    for (int i = t; i < 2016; i += 128) {
        int m = i >> 5, d = i & 31;
        sm[APO + m * 36 + d]        = relw[i];
        sm[APO + 2268 + m * 36 + d] = relh[i];
    }
    __syncthreads();

    // eh2[qi][xk] = eh[qi][xk - hq(qi) + 31]
    for (int e = t; e < 2048; e += 128) {
        int qi = e >> 5, xk = e & 31;
        int m = xk - (2 * bx + (qi >> 5)) + 31;
        const float* qp = sm + qi * 36;
        const float* rp = sm + APO + 2268 + m * 36;
        float s = 0.f;
#pragma unroll
        for (int d = 0; d < 32; d += 4) {
            float4 q4 = *(const float4*)(qp + d);
            float4 r4 = *(const float4*)(rp + d);
            s += q4.x * r4.x + q4.y * r4.y + q4.z * r4.z + q4.w * r4.w;
        }
        sm[AEH + e] = s;
    }

    const int qiA = qrow + gid, qiB = qiA + 8;
    unsigned qa[4][4];
#pragma unroll
    for (int ks = 0; ks < 4; ks++) {
        int kd = ks * 8;
        qa[ks][0] = cvt_tf32(sm[qiA * 36 + kd + tig]);
        qa[ks][1] = cvt_tf32(sm[qiB * 36 + kd + tig]);
        qa[ks][2] = cvt_tf32(sm[qiA * 36 + kd + tig + 4]);
        qa[ks][3] = cvt_tf32(sm[qiB * 36 + kd + tig + 4]);
    }
    float ewreg[2][8];
#pragma unroll
    for (int rr = 0; rr < 2; rr++) {
        int qi = rr ? qiB : qiA;
        const float* qp = sm + qi * 36;
#pragma unroll
        for (int e = 0; e < 8; e++) {
            int yk = (e >> 1) * 8 + tig * 2 + (e & 1);
            int m = yk - (qi & 31) + 31;
            const float* rp = sm + APO + m * 36;
            float s = 0.f;
#pragma unroll
            for (int d = 0; d < 32; d += 4) {
                float4 q4 = *(const float4*)(qp + d);
                float4 r4 = *(const float4*)(rp + d);
                s += q4.x * r4.x + q4.y * r4.y + q4.z * r4.z + q4.w * r4.w;
            }
            ewreg[rr][e] = s;
        }
    }
    __syncthreads();

    // stage tile 0
    {
        float4 kr0[4], vr0[4];
#pragma unroll
        for (int j = 0; j < 4; j++) {
            int fi = j * 128 + t, d = fi >> 4, c = (fi & 15) * 4;
            kr0[j] = *(const float4*)(kb + d * 1024 + c);
            vr0[j] = *(const float4*)(vb + d * 1024 + c);
        }
#pragma unroll
        for (int j = 0; j < 4; j++) {
            int fi = j * 128 + t, d = fi >> 4, c = (fi & 15) * 4;
            *(float4*)&sm[d * 72 + c]        = kr0[j];
            *(float4*)&sm[2304 + d * 72 + c] = vr0[j];
        }
    }
    __syncthreads();

    float sA = 0.f, sB = 0.f;     // fixed-max softmax (logits bounded; no overflow in fp32)
    float4 oc[2][2];
#pragma unroll
    for (int mt = 0; mt < 2; mt++)
#pragma unroll
        for (int n2 = 0; n2 < 2; n2++) oc[mt][n2] = make_float4(0.f, 0.f, 0.f, 0.f);

    float4 kr[4], vr[4];
    for (int tile = 0; tile < 16; tile++) {
        const bool more = (tile < 15);
        if (more) {
            int k0n = (tile + 1) * 64;
#pragma unroll
            for (int j = 0; j < 4; j++) {
                int fi = j * 128 + t, d = fi >> 4, c = (fi & 15) * 4;
                kr[j] = *(const float4*)(kb + d * 1024 + k0n + c);
                vr[j] = *(const float4*)(vb + d * 1024 + k0n + c);
            }
        }

        float4 sc4[8];
#pragma unroll
        for (int nt = 0; nt < 8; nt++) sc4[nt] = make_float4(0.f, 0.f, 0.f, 0.f);
#pragma unroll
        for (int ks = 0; ks < 4; ks++) {
            int kd = ks * 8;
#pragma unroll
            for (int nt = 0; nt < 8; nt++) {
                unsigned b0 = __float_as_uint(sm[(kd + tig) * 72 + nt * 8 + gid]);
                unsigned b1 = __float_as_uint(sm[(kd + tig + 4) * 72 + nt * 8 + gid]);
                mma_tf32(sc4[nt], qa[ks][0], qa[ks][1], qa[ks][2], qa[ks][3], b0, b1);
            }
        }

        // rel add + exp (no running max), accumulate row sums, store P
        int xk = tile * 2;
        float ehA0 = sm[AEH + qiA * 32 + xk];
        float ehA1 = sm[AEH + qiA * 32 + xk + 1];
        float ehB0 = sm[AEH + qiB * 32 + xk];
        float ehB1 = sm[AEH + qiB * 32 + xk + 1];
        float rsA = 0.f, rsB = 0.f;
#pragma unroll
        for (int nt = 0; nt < 8; nt++) {
            float ha = (nt < 4) ? ehA0 : ehA1;
            float hb = (nt < 4) ? ehB0 : ehB1;
            float px = __expf(sc4[nt].x + ewreg[0][(nt & 3) * 2 + 0] + ha);
            float py = __expf(sc4[nt].y + ewreg[0][(nt & 3) * 2 + 1] + ha);
            float pz = __expf(sc4[nt].z + ewreg[1][(nt & 3) * 2 + 0] + hb);
            float pw = __expf(sc4[nt].w + ewreg[1][(nt & 3) * 2 + 1] + hb);
            rsA += px + py; rsB += pz + pw;
            int cc = nt * 8 + 2 * tig;
            *(float2*)&sm[APO + qiA * 72 + cc] = make_float2(px, py);
            *(float2*)&sm[APO + qiB * 72 + cc] = make_float2(pz, pw);
        }
        sA += rsA; sB += rsB;
        __syncwarp();

        // O^T += V P^T
#pragma unroll
        for (int ks = 0; ks < 8; ks++) {
            int kk = ks * 8;
            unsigned p0[2], p1[2];
#pragma unroll
            for (int n2 = 0; n2 < 2; n2++) {
                p0[n2] = __float_as_uint(sm[APO + (qrow + n2 * 8 + gid) * 72 + kk + tig]);
                p1[n2] = __float_as_uint(sm[APO + (qrow + n2 * 8 + gid) * 72 + kk + tig + 4]);
            }
#pragma unroll
            for (int mt = 0; mt < 2; mt++) {
                int dv0 = mt * 16;
                unsigned a0 = __float_as_uint(sm[2304 + (dv0 + gid) * 72 + kk + tig]);
                unsigned a1 = __float_as_uint(sm[2304 + (dv0 + gid + 8) * 72 + kk + tig]);
                unsigned a2 = __float_as_uint(sm[2304 + (dv0 + gid) * 72 + kk + tig + 4]);
                unsigned a3 = __float_as_uint(sm[2304 + (dv0 + gid + 8) * 72 + kk + tig + 4]);
                mma_tf32(oc[mt][0], a0, a1, a2, a3, p0[0], p1[0]);
                mma_tf32(oc[mt][1], a0, a1, a2, a3, p0[1], p1[1]);
            }
        }

        __syncthreads();
        if (more) {
#pragma unroll
            for (int j = 0; j < 4; j++) {
                int fi = j * 128 + t, d = fi >> 4, c = (fi & 15) * 4;
                *(float4*)&sm[d * 72 + c]        = kr[j];
                *(float4*)&sm[2304 + d * 72 + c] = vr[j];
            }
        }
        __syncthreads();
    }

    // reduce row sums across tig lanes, broadcast 1/sum
    sA += __shfl_xor_sync(0xffffffffu, sA, 1);
    sA += __shfl_xor_sync(0xffffffffu, sA, 2);
    sB += __shfl_xor_sync(0xffffffffu, sB, 1);
    sB += __shfl_xor_sync(0xffffffffu, sB, 2);
    if (tig == 0) { sm[ASC + qiA] = 1.f / sA; sm[ASC + qiB] = 1.f / sB; }
    __syncwarp();
    float si[2][2];
#pragma unroll
    for (int n2 = 0; n2 < 2; n2++)
#pragma unroll
        for (int j = 0; j < 2; j++)
            si[n2][j] = sm[ASC + qrow + n2 * 8 + 2 * tig + j];
    float* ob = attn_out + ((long long)b * 256 + h * 32) * 1024 + q0;
#pragma unroll
    for (int mt = 0; mt < 2; mt++)
#pragma unroll
        for (int n2 = 0; n2 < 2; n2++) {
            int dv0 = mt * 16 + gid;
            int qq = qrow + n2 * 8 + 2 * tig;
            *(float2*)&ob[(long long)dv0 * 1024 + qq] =
                make_float2(oc[mt][n2].x * si[n2][0], oc[mt][n2].y * si[n2][1]);
            *(float2*)&ob[(long long)(dv0 + 8) * 1024 + qq] =
                make_float2(oc[mt][n2].z * si[n2][0], oc[mt][n2].w * si[n2][1]);
        }
}

// ---------------- launch: R9 schedule (conv on one side stream) ----------------
extern "C" void kernel_launch(void* const* d_in, const int* in_sizes, int n_in,
                              void* d_out, int out_size) {
    const float* x      = (const float*)d_in[0];
    const float* w_qkv  = (const float*)d_in[1];
    const float* b_qkv  = (const float*)d_in[2];
    const float* w_attn = (const float*)d_in[3];
    const float* b_attn = (const float*)d_in[4];
    const float* w_out  = (const float*)d_in[5];
    const float* b_out  = (const float*)d_in[6];
    const float* relw   = (const float*)d_in[7];
    const float* relh   = (const float*)d_in[8];
    float* out = (float*)d_out;

    float *qkv, *attn;
    cudaGetSymbolAddress((void**)&qkv,  g_qkv);
    cudaGetSymbolAddress((void**)&attn, g_attn);

    const int A_SMEM = A_SM_FLOATS * 4;   // 45312
    cudaFuncSetAttribute(attn_mma, cudaFuncAttributeMaxDynamicSharedMemorySize, A_SMEM);

    cudaStream_t s1;
    cudaEvent_t e0, e1;
    cudaStreamCreateWithFlags(&s1, cudaStreamNonBlocking);
    cudaEventCreateWithFlags(&e0, cudaEventDisableTiming);
    cudaEventCreateWithFlags(&e1, cudaEventDisableTiming);

    // fork: conv path on side stream
    cudaEventRecord(e0, 0);
    cudaStreamWaitEvent(s1, e0, 0);
    conv_gemm_tf32<<<dim3(8, 2, 8), 256, 0, s1>>>(w_out, x, out, b_out, 512LL * 1024);
    cudaEventRecord(e1, s1);

    // main chain on the capture stream
    sgemm_tf32<<<dim3(8, 6, 8), 256>>>(w_qkv, x, qkv, b_qkv,
                                       768, 1024, 256,
                                       256LL * 1024, 768LL * 1024, 0,
                                       0.17677669529663687f, 256);
    attn_mma<<<dim3(16, 64), 128, A_SMEM>>>(qkv, relw, relh, attn);
    sgemm_tf32<<<dim3(8, 2, 8), 256>>>(w_attn, attn, out, b_attn,
                                       256, 1024, 256,
                                       256LL * 1024, 512LL * 1024, 256,
                                       1.f, 0);

    // join
    cudaStreamWaitEvent(0, e1, 0);

    cudaStreamCaptureStatus st = cudaStreamCaptureStatusNone;
    cudaStreamIsCapturing(s1, &st);
    if (st == cudaStreamCaptureStatusNone) {
        cudaStreamDestroy(s1);
        cudaEventDestroy(e0);
        cudaEventDestroy(e1);
    }
}